// round 15
// baseline (speedup 1.0000x reference)
#include <cuda_runtime.h>
#include <cuda_bf16.h>
#include <math.h>
#include <stdint.h>

// Problem constants
#define BB 4
#define SS 1024
#define DD 1024
#define HH 16
#define DFF 4096
#define NLAYERS 4
#define MM (BB*SS)          // 4096 rows

// ---------------------------------------------------------------------------
// Scratch (static device globals -- no allocation allowed)
// ---------------------------------------------------------------------------
__device__ float g_x  [(size_t)MM * DD];        // activations (fp32, residual)
__device__ float g_tmp[(size_t)MM * DD];        // pre-LN buffer
// split-bf16 activation buffers
__device__ __nv_bfloat16 g_qkvh[(size_t)MM * 3 * DD];     // qkv hi (Q pre-scaled)
__device__ __nv_bfloat16 g_qkvl[(size_t)MM * 3 * DD];     // qkv lo
__device__ __nv_bfloat16 g_xh[(size_t)MM * DD];           // x hi (LN output)
__device__ __nv_bfloat16 g_xl[(size_t)MM * DD];           // x lo
__device__ __nv_bfloat16 g_oh[(size_t)MM * DD];           // attn-out hi
__device__ __nv_bfloat16 g_ol[(size_t)MM * DD];           // attn-out lo
__device__ __nv_bfloat16 g_ah[(size_t)MM * DFF];          // FF hidden hi
__device__ __nv_bfloat16 g_al[(size_t)MM * DFF];          // FF hidden lo
__device__ __nv_bfloat16 g_wh[(size_t)4 * 1024 * 1024];   // W hi
__device__ __nv_bfloat16 g_wl[(size_t)4 * 1024 * 1024];   // W lo

// ---------------------------------------------------------------------------
// Helpers
// ---------------------------------------------------------------------------
__device__ __forceinline__ uint32_t smem_u32(const void* p) {
    uint32_t a;
    asm("{ .reg .u64 t; cvta.to.shared.u64 t, %1; cvt.u32.u64 %0, t; }"
        : "=r"(a) : "l"(p));
    return a;
}
__device__ __forceinline__ uint32_t swz(uint32_t off) {
    return off ^ ((off >> 3) & 0x70);
}
// pack two floats into bf16x2 (hi) and residual bf16x2 (lo)
__device__ __forceinline__ void split2(float x, float y, uint32_t& H, uint32_t& L) {
    __nv_bfloat162 h = __floats2bfloat162_rn(x, y);
    __nv_bfloat162 l = __floats2bfloat162_rn(x - __low2float(h), y - __high2float(h));
    H = *(uint32_t*)&h;
    L = *(uint32_t*)&l;
}

#define CP_ASYNC16(dst, src) \
    asm volatile("cp.async.cg.shared.global [%0], [%1], 16;" :: "r"(dst), "l"(src))
#define CP_COMMIT() asm volatile("cp.async.commit_group;")
#define CP_WAIT1()  asm volatile("cp.async.wait_group 1;")
#define CP_WAIT0()  asm volatile("cp.async.wait_group 0;")

__device__ __forceinline__ void ldsm4(uint32_t* r, uint32_t addr) {
    asm volatile("ldmatrix.sync.aligned.m8n8.x4.shared.b16 {%0,%1,%2,%3}, [%4];"
        : "=r"(r[0]), "=r"(r[1]), "=r"(r[2]), "=r"(r[3]) : "r"(addr));
}
__device__ __forceinline__ void ldsm4t(uint32_t* r, uint32_t addr) {
    asm volatile("ldmatrix.sync.aligned.m8n8.x4.trans.shared.b16 {%0,%1,%2,%3}, [%4];"
        : "=r"(r[0]), "=r"(r[1]), "=r"(r[2]), "=r"(r[3]) : "r"(addr));
}
__device__ __forceinline__ void mma16816(float* d, const uint32_t* a, const uint32_t* b) {
    asm volatile(
        "mma.sync.aligned.m16n8k16.row.col.f32.bf16.bf16.f32 "
        "{%0,%1,%2,%3}, {%4,%5,%6,%7}, {%8,%9}, {%0,%1,%2,%3};"
        : "+f"(d[0]), "+f"(d[1]), "+f"(d[2]), "+f"(d[3])
        : "r"(a[0]), "r"(a[1]), "r"(a[2]), "r"(a[3]), "r"(b[0]), "r"(b[1]));
}

// ---------------------------------------------------------------------------
// fp32 -> (hi, lo) bf16 split (weights only)
// ---------------------------------------------------------------------------
__global__ __launch_bounds__(256)
void split_kernel(const float4* __restrict__ in, uint2* __restrict__ hi,
                  uint2* __restrict__ lo, int n4)
{
    int i = blockIdx.x * 256 + threadIdx.x;
    if (i >= n4) return;
    float4 v = in[i];
    uint2 H, L;
    split2(v.x, v.y, H.x, L.x);
    split2(v.z, v.w, H.y, L.y);
    hi[i] = H;
    lo[i] = L;
}

// ---------------------------------------------------------------------------
// Persistent tensor-core split-bf16 GEMM: C[M,N] = A[M,K] @ B[N,K]^T, M=4096.
// grid = #SMs; each CTA walks tiles bid, bid+nsm, ... with a FLAT chunk
// stream: the 3-stage cp.async pipeline crosses tile boundaries, so the next
// tile's loads overlap the current tile's epilogue. 16 warps, warp tile 32x32.
// ---------------------------------------------------------------------------
enum { EPI_BIAS = 0, EPI_RELU = 1, EPI_RES = 2, EPI_QKV = 3 };

#define TB 16384                       // one 128x64 bf16 tile
#define GEMM_SMEM (3 * 4 * TB)         // 196608 B

template<int EPI>
__global__ __launch_bounds__(512, 1)
void gemm_tc(const __nv_bfloat16* __restrict__ Ah, const __nv_bfloat16* __restrict__ Al,
             const __nv_bfloat16* __restrict__ Bh, const __nv_bfloat16* __restrict__ Bl,
             const float* __restrict__ bias, const float* __restrict__ Res,
             float* __restrict__ C,
             __nv_bfloat16* __restrict__ Ch, __nv_bfloat16* __restrict__ Cl,
             int K, int N, int total_tiles, int gx)
{
    extern __shared__ char smg[];
    const uint32_t sbase = smem_u32(smg);
    const int tid  = threadIdx.x;
    const int lane = tid & 31, wid = tid >> 5;       // 16 warps
    const int bid = blockIdx.x, nct = gridDim.x;
    const int wm = (wid & 3) << 5;
    const int wn = (wid >> 2) << 5;

    const int lrow = tid >> 3;         // 0..63
    const int lkg  = tid & 7;          // 16B group within row
    uint32_t dbase[4];
    {
        uint32_t sw = swz(lrow * 128 + lkg * 16);
#pragma unroll
        for (int t = 0; t < 4; t++) dbase[t] = sbase + t * TB + sw;
    }

    const int nc = K >> 6;
    const int my_tiles = (total_tiles - bid + nct - 1) / nct;
    const int G = my_tiles * nc;       // flat chunk count for this CTA

    // issue loads for flat chunk g into stage s
    auto LOADC = [&](int g, int s) {
        const int ti = g / nc;                     // local tile index
        const int c  = g - ti * nc;                // k-chunk within tile
        const int gt = bid + ti * nct;             // global tile
        const int m0 = (gt / gx) << 7;
        const int n0 = (gt - (gt / gx) * gx) << 7;
        const size_t kb = ((size_t)c << 6) + lkg * 8;
        const __nv_bfloat16* s0 = Ah + (size_t)(m0 + lrow) * K + kb;
        const __nv_bfloat16* s1 = Al + (size_t)(m0 + lrow) * K + kb;
        const __nv_bfloat16* s2 = Bh + (size_t)(n0 + lrow) * K + kb;
        const __nv_bfloat16* s3 = Bl + (size_t)(n0 + lrow) * K + kb;
        const uint32_t so = (uint32_t)s * (4 * TB);
        const size_t half = (size_t)64 * K;
        CP_ASYNC16(dbase[0] + so,        s0);
        CP_ASYNC16(dbase[0] + so + 8192, s0 + half);
        CP_ASYNC16(dbase[1] + so,        s1);
        CP_ASYNC16(dbase[1] + so + 8192, s1 + half);
        CP_ASYNC16(dbase[2] + so,        s2);
        CP_ASYNC16(dbase[2] + so + 8192, s2 + half);
        CP_ASYNC16(dbase[3] + so,        s3);
        CP_ASYNC16(dbase[3] + so + 8192, s3 + half);
    };

    float acc[2][4][4];
#pragma unroll
    for (int mi = 0; mi < 2; mi++)
#pragma unroll
        for (int ni = 0; ni < 4; ni++)
#pragma unroll
            for (int e = 0; e < 4; e++) acc[mi][ni][e] = 0.f;

    if (G == 0) return;
    LOADC(0, 0); CP_COMMIT();
    if (G > 1) LOADC(1, 1);
    CP_COMMIT();

    const uint32_t arow = wm + (lane & 15);
    const uint32_t brow = wn + (lane & 15);
    const uint32_t axor = (arow & 7) << 4;
    const uint32_t bxor = (brow & 7) << 4;
    const uint32_t chalf = (lane >> 4) << 4;
    const int g0 = lane >> 2, tig = lane & 3;

    for (int g = 0; g < G; g++) {
        CP_WAIT1();
        __syncthreads();
        if (g + 2 < G) LOADC(g + 2, (g + 2) % 3);
        CP_COMMIT();

        const uint32_t st = (uint32_t)(g % 3) * (4 * TB);
        const uint32_t aAh = sbase + st + arow * 128;
        const uint32_t aAl = aAh + TB;
        const uint32_t aBh = sbase + st + 2 * TB + brow * 128;
        const uint32_t aBl = aBh + TB;

#pragma unroll
        for (int kk = 0; kk < 4; kk++) {
            const uint32_t ca = (kk * 32 + chalf) ^ axor;
            const uint32_t cb = (kk * 32 + chalf) ^ bxor;
            uint32_t ah[2][4], al[2][4], bh[4][2], bl[4][2];
#pragma unroll
            for (int mi = 0; mi < 2; mi++) {
                ldsm4(ah[mi], aAh + mi * (16 * 128) + ca);
                ldsm4(al[mi], aAl + mi * (16 * 128) + ca);
            }
#pragma unroll
            for (int nh = 0; nh < 2; nh++) {
                uint32_t r[4];
                ldsm4(r, aBh + nh * (16 * 128) + cb);
                bh[2*nh][0] = r[0]; bh[2*nh][1] = r[2];
                bh[2*nh+1][0] = r[1]; bh[2*nh+1][1] = r[3];
                ldsm4(r, aBl + nh * (16 * 128) + cb);
                bl[2*nh][0] = r[0]; bl[2*nh][1] = r[2];
                bl[2*nh+1][0] = r[1]; bl[2*nh+1][1] = r[3];
            }
#pragma unroll
            for (int mi = 0; mi < 2; mi++)
#pragma unroll
                for (int ni = 0; ni < 4; ni++)
                    mma16816(acc[mi][ni], ah[mi], bh[ni]);
#pragma unroll
            for (int mi = 0; mi < 2; mi++)
#pragma unroll
                for (int ni = 0; ni < 4; ni++)
                    mma16816(acc[mi][ni], ah[mi], bl[ni]);
#pragma unroll
            for (int mi = 0; mi < 2; mi++)
#pragma unroll
                for (int ni = 0; ni < 4; ni++)
                    mma16816(acc[mi][ni], al[mi], bh[ni]);
        }

        // ---- tile boundary: epilogue (register->gmem; overlaps next loads) --
        if (((g + 1) - ((g + 1) / nc) * nc) == 0) {
            const int gt = bid + (g / nc) * nct;
            const int m0 = (gt / gx) << 7;
            const int n0 = (gt - (gt / gx) * gx) << 7;
#pragma unroll
            for (int mi = 0; mi < 2; mi++) {
                const int r1 = m0 + wm + mi * 16 + g0;
                const int r2 = r1 + 8;
#pragma unroll
                for (int ni = 0; ni < 4; ni++) {
                    const int col = n0 + wn + ni * 8 + tig * 2;
                    float2 bv = *(const float2*)(bias + col);
                    float2 v0 = make_float2(acc[mi][ni][0] + bv.x, acc[mi][ni][1] + bv.y);
                    float2 v1 = make_float2(acc[mi][ni][2] + bv.x, acc[mi][ni][3] + bv.y);
                    if (EPI == EPI_RELU) {
                        v0.x = fmaxf(v0.x, 0.f); v0.y = fmaxf(v0.y, 0.f);
                        v1.x = fmaxf(v1.x, 0.f); v1.y = fmaxf(v1.y, 0.f);
                        uint32_t H, L;
                        split2(v0.x, v0.y, H, L);
                        *(uint32_t*)(Ch + (size_t)r1 * N + col) = H;
                        *(uint32_t*)(Cl + (size_t)r1 * N + col) = L;
                        split2(v1.x, v1.y, H, L);
                        *(uint32_t*)(Ch + (size_t)r2 * N + col) = H;
                        *(uint32_t*)(Cl + (size_t)r2 * N + col) = L;
                    } else if (EPI == EPI_QKV) {
                        const float s = (col < 1024) ? 0.125f : 1.0f;
                        uint32_t H, L;
                        split2(v0.x * s, v0.y * s, H, L);
                        *(uint32_t*)(Ch + (size_t)r1 * N + col) = H;
                        *(uint32_t*)(Cl + (size_t)r1 * N + col) = L;
                        split2(v1.x * s, v1.y * s, H, L);
                        *(uint32_t*)(Ch + (size_t)r2 * N + col) = H;
                        *(uint32_t*)(Cl + (size_t)r2 * N + col) = L;
                    } else {
                        if (EPI == EPI_RES) {
                            float2 q0 = *(const float2*)(Res + (size_t)r1 * N + col);
                            float2 q1 = *(const float2*)(Res + (size_t)r2 * N + col);
                            v0.x += q0.x; v0.y += q0.y; v1.x += q1.x; v1.y += q1.y;
                        }
                        *(float2*)(C + (size_t)r1 * N + col) = v0;
                        *(float2*)(C + (size_t)r2 * N + col) = v1;
                    }
                }
            }
#pragma unroll
            for (int mi = 0; mi < 2; mi++)
#pragma unroll
                for (int ni = 0; ni < 4; ni++)
#pragma unroll
                    for (int e = 0; e < 4; e++) acc[mi][ni][e] = 0.f;
        }
    }
}

// ---------------------------------------------------------------------------
// Tensor-core block-causal flash attention (split bf16, mma.m16n8k16).
// CTA = 128 threads (4 warps), one 64-row q-block for one (b,h).
// Heavy q-blocks launch first (jq reversed) to shorten the makespan tail.
// ---------------------------------------------------------------------------
#define ATTN_SMEM 49152

__global__ __launch_bounds__(128, 4)
void attn_tc(const __nv_bfloat16* __restrict__ qvh, const __nv_bfloat16* __restrict__ qvl,
             __nv_bfloat16* __restrict__ oh, __nv_bfloat16* __restrict__ ol)
{
    extern __shared__ char smx[];
    const uint32_t sb  = smem_u32(smx);
    const uint32_t sQh = sb, sQl = sb + 8192;
    const uint32_t sKh = sb + 16384, sKl = sb + 24576;
    const uint32_t sVh = sb + 32768, sVl = sb + 40960;

    const int jq = gridDim.x - 1 - blockIdx.x;     // heaviest first
    const int b  = blockIdx.y >> 4, h = blockIdx.y & 15;
    const int tid = threadIdx.x, lane = tid & 31, w = tid >> 5;
    const int g = lane >> 2, tig = lane & 3;

    const int lrow = tid >> 3;                 // 0..15
    const uint32_t ld_sw = swz(lrow * 128 + (tid & 7) * 16);
    const size_t qtok = (size_t)(b * SS + jq * 64 + lrow) * 3072 + h * 64 + (tid & 7) * 8;
    const size_t ktokb = (size_t)(b * SS + lrow) * 3072 + 1024 + h * 64 + (tid & 7) * 8;

#pragma unroll
    for (int p = 0; p < 4; p++) {
        CP_ASYNC16(sQh + ld_sw + p * 2048, qvh + qtok + (size_t)p * 16 * 3072);
        CP_ASYNC16(sQl + ld_sw + p * 2048, qvl + qtok + (size_t)p * 16 * 3072);
    }
#pragma unroll
    for (int p = 0; p < 4; p++) {
        const size_t t = ktokb + (size_t)p * 16 * 3072;
        CP_ASYNC16(sKh + ld_sw + p * 2048, qvh + t);
        CP_ASYNC16(sKl + ld_sw + p * 2048, qvl + t);
        CP_ASYNC16(sVh + ld_sw + p * 2048, qvh + t + 1024);
        CP_ASYNC16(sVl + ld_sw + p * 2048, qvl + t + 1024);
    }
    CP_COMMIT();

    float accO[8][4];
#pragma unroll
    for (int ni = 0; ni < 8; ni++)
#pragma unroll
        for (int e = 0; e < 4; e++) accO[ni][e] = 0.f;
    float mrow[2] = {-INFINITY, -INFINITY};
    float lsum[2] = {0.f, 0.f};

    const uint32_t arow  = 16 * w + (lane & 15);
    const uint32_t krow  = (lane & 15);
    const uint32_t sxor  = (lane & 7) << 4;
    const uint32_t chalf = (lane >> 4) << 4;
    const uint32_t aQh = sQh + arow * 128, aQl = sQl + arow * 128;

    for (int kb = 0; kb <= jq; kb++) {
        CP_WAIT0();
        __syncthreads();

        float accS[8][4];
#pragma unroll
        for (int ni = 0; ni < 8; ni++)
#pragma unroll
            for (int e = 0; e < 4; e++) accS[ni][e] = 0.f;

#pragma unroll
        for (int ks = 0; ks < 4; ks++) {
            const uint32_t cc = (ks * 32 + chalf) ^ sxor;
            uint32_t qah[4], qal[4];
            ldsm4(qah, aQh + cc);
            ldsm4(qal, aQl + cc);
            uint32_t kbh[8][2], kbl[8][2];
#pragma unroll
            for (int kn = 0; kn < 4; kn++) {
                uint32_t r[4];
                ldsm4(r, sKh + (kn * 16 + krow) * 128 + cc);
                kbh[2*kn][0] = r[0]; kbh[2*kn][1] = r[2];
                kbh[2*kn+1][0] = r[1]; kbh[2*kn+1][1] = r[3];
                ldsm4(r, sKl + (kn * 16 + krow) * 128 + cc);
                kbl[2*kn][0] = r[0]; kbl[2*kn][1] = r[2];
                kbl[2*kn+1][0] = r[1]; kbl[2*kn+1][1] = r[3];
            }
#pragma unroll
            for (int ni = 0; ni < 8; ni++) mma16816(accS[ni], qah, kbh[ni]);
#pragma unroll
            for (int ni = 0; ni < 8; ni++) mma16816(accS[ni], qah, kbl[ni]);
#pragma unroll
            for (int ni = 0; ni < 8; ni++) mma16816(accS[ni], qal, kbh[ni]);
        }
        __syncthreads();

        if (kb < jq) {
            const size_t tn = ktokb + (size_t)(kb + 1) * 64 * 3072;
#pragma unroll
            for (int p = 0; p < 4; p++) {
                CP_ASYNC16(sKh + ld_sw + p * 2048, qvh + tn + (size_t)p * 16 * 3072);
                CP_ASYNC16(sKl + ld_sw + p * 2048, qvl + tn + (size_t)p * 16 * 3072);
            }
            CP_COMMIT();
        }

#pragma unroll
        for (int e = 0; e < 2; e++) {
            float mb = accS[0][2*e];
#pragma unroll
            for (int ni = 0; ni < 8; ni++) {
                mb = fmaxf(mb, accS[ni][2*e]);
                mb = fmaxf(mb, accS[ni][2*e+1]);
            }
            mb = fmaxf(mb, __shfl_xor_sync(0xffffffffu, mb, 1));
            mb = fmaxf(mb, __shfl_xor_sync(0xffffffffu, mb, 2));
            const float mnew = fmaxf(mrow[e], mb);
            const float alpha = __expf(mrow[e] - mnew);
            float rs = 0.f;
#pragma unroll
            for (int ni = 0; ni < 8; ni++) {
                float p0 = __expf(accS[ni][2*e]   - mnew);
                float p1 = __expf(accS[ni][2*e+1] - mnew);
                accS[ni][2*e] = p0; accS[ni][2*e+1] = p1;
                rs += p0 + p1;
            }
            rs += __shfl_xor_sync(0xffffffffu, rs, 1);
            rs += __shfl_xor_sync(0xffffffffu, rs, 2);
            lsum[e] = lsum[e] * alpha + rs;
            mrow[e] = mnew;
#pragma unroll
            for (int ni = 0; ni < 8; ni++) {
                accO[ni][2*e]   *= alpha;
                accO[ni][2*e+1] *= alpha;
            }
        }

#pragma unroll
        for (int j = 0; j < 4; j++) {
            uint32_t ph[4], pl[4];
            split2(accS[2*j][0],   accS[2*j][1],   ph[0], pl[0]);
            split2(accS[2*j][2],   accS[2*j][3],   ph[1], pl[1]);
            split2(accS[2*j+1][0], accS[2*j+1][1], ph[2], pl[2]);
            split2(accS[2*j+1][2], accS[2*j+1][3], ph[3], pl[3]);
            const uint32_t vbase = (j * 16 + krow) * 128;
            uint32_t bvh[8][2], bvl[8][2];
#pragma unroll
            for (int ng = 0; ng < 4; ng++) {
                const uint32_t cc = (ng * 32 + chalf) ^ sxor;
                uint32_t r[4];
                ldsm4t(r, sVh + vbase + cc);
                bvh[2*ng][0] = r[0]; bvh[2*ng][1] = r[1];
                bvh[2*ng+1][0] = r[2]; bvh[2*ng+1][1] = r[3];
                ldsm4t(r, sVl + vbase + cc);
                bvl[2*ng][0] = r[0]; bvl[2*ng][1] = r[1];
                bvl[2*ng+1][0] = r[2]; bvl[2*ng+1][1] = r[3];
            }
#pragma unroll
            for (int ni = 0; ni < 8; ni++) mma16816(accO[ni], ph, bvh[ni]);
#pragma unroll
            for (int ni = 0; ni < 8; ni++) mma16816(accO[ni], ph, bvl[ni]);
#pragma unroll
            for (int ni = 0; ni < 8; ni++) mma16816(accO[ni], pl, bvh[ni]);
        }
        __syncthreads();

        if (kb < jq) {
            const size_t tn = ktokb + (size_t)(kb + 1) * 64 * 3072 + 1024;
#pragma unroll
            for (int p = 0; p < 4; p++) {
                CP_ASYNC16(sVh + ld_sw + p * 2048, qvh + tn + (size_t)p * 16 * 3072);
                CP_ASYNC16(sVl + ld_sw + p * 2048, qvl + tn + (size_t)p * 16 * 3072);
            }
            CP_COMMIT();
        }
    }

    const size_t orow0 = (size_t)(b * SS + jq * 64 + 16 * w + g);
#pragma unroll
    for (int e = 0; e < 2; e++) {
        const float inv = 1.0f / lsum[e];
        const size_t rbase = (orow0 + 8 * e) * (size_t)DD + h * 64 + tig * 2;
#pragma unroll
        for (int ni = 0; ni < 8; ni++) {
            uint32_t H, L;
            split2(accO[ni][2*e] * inv, accO[ni][2*e+1] * inv, H, L);
            *(uint32_t*)(oh + rbase + ni * 8) = H;
            *(uint32_t*)(ol + rbase + ni * 8) = L;
        }
    }
}

// ---------------------------------------------------------------------------
// LayerNorm over D=1024, one block (256 threads) per row.
// ---------------------------------------------------------------------------
__global__ __launch_bounds__(256)
void ln_kernel(const float* __restrict__ in, const float* __restrict__ w,
               const float* __restrict__ b, float* __restrict__ out,
               __nv_bfloat16* __restrict__ oh, __nv_bfloat16* __restrict__ ol)
{
    __shared__ float s_sum[8], s_sq[8], s_bc[2];
    const int row = blockIdx.x, tid = threadIdx.x;
    float4 v = ((const float4*)(in + (size_t)row * 1024))[tid];
    float s = v.x + v.y + v.z + v.w;
    float q = v.x * v.x + v.y * v.y + v.z * v.z + v.w * v.w;
#pragma unroll
    for (int o = 16; o; o >>= 1) {
        s += __shfl_xor_sync(0xffffffffu, s, o);
        q += __shfl_xor_sync(0xffffffffu, q, o);
    }
    if ((tid & 31) == 0) { s_sum[tid >> 5] = s; s_sq[tid >> 5] = q; }
    __syncthreads();
    if (tid == 0) {
        float ts = 0.f, tq = 0.f;
#pragma unroll
        for (int i = 0; i < 8; i++) { ts += s_sum[i]; tq += s_sq[i]; }
        float mu  = ts * (1.f / 1024.f);
        float var = tq * (1.f / 1024.f) - mu * mu;
        s_bc[0] = mu;
        s_bc[1] = rsqrtf(var + 1e-5f);
    }
    __syncthreads();
    float mu = s_bc[0], rs = s_bc[1];
    float4 wv = ((const float4*)w)[tid];
    float4 bv = ((const float4*)b)[tid];
    float4 ov;
    ov.x = (v.x - mu) * rs * wv.x + bv.x;
    ov.y = (v.y - mu) * rs * wv.y + bv.y;
    ov.z = (v.z - mu) * rs * wv.z + bv.z;
    ov.w = (v.w - mu) * rs * wv.w + bv.w;
    ((float4*)(out + (size_t)row * 1024))[tid] = ov;
    uint2 H, L;
    split2(ov.x, ov.y, H.x, L.x);
    split2(ov.z, ov.w, H.y, L.y);
    ((uint2*)(oh + (size_t)row * 1024))[tid] = H;
    ((uint2*)(ol + (size_t)row * 1024))[tid] = L;
}

// initial copy: x -> working fp32 buffer + split bf16
__global__ __launch_bounds__(256)
void init_kernel(const float4* __restrict__ s, float4* __restrict__ d,
                 uint2* __restrict__ hi, uint2* __restrict__ lo)
{
    int i = blockIdx.x * 256 + threadIdx.x;
    float4 v = s[i];
    d[i] = v;
    uint2 H, L;
    split2(v.x, v.y, H.x, L.x);
    split2(v.z, v.w, H.y, L.y);
    hi[i] = H;
    lo[i] = L;
}

// ---------------------------------------------------------------------------
// Host orchestration (graph-capturable: kernel launches only)
// ---------------------------------------------------------------------------
extern "C" void kernel_launch(void* const* d_in, const int* in_sizes, int n_in,
                              void* d_out, int out_size)
{
    (void)in_sizes; (void)n_in; (void)out_size;
    const float* x_in = (const float*)d_in[0];
    const float* ipw  = (const float*)d_in[1];   // [L,3072,1024]
    const float* ipb  = (const float*)d_in[2];   // [L,3072]
    const float* ow   = (const float*)d_in[3];   // [L,1024,1024]
    const float* ob   = (const float*)d_in[4];   // [L,1024]
    const float* n1w  = (const float*)d_in[5];
    const float* n1b  = (const float*)d_in[6];
    const float* f1w  = (const float*)d_in[7];   // [L,4096,1024]
    const float* f1b  = (const float*)d_in[8];   // [L,4096]
    const float* f2w  = (const float*)d_in[9];   // [L,1024,4096]
    const float* f2b  = (const float*)d_in[10];  // [L,1024]
    const float* n2w  = (const float*)d_in[11];
    const float* n2b  = (const float*)d_in[12];
    float* out = (float*)d_out;

    float *px, *ptmp;
    __nv_bfloat16 *pqh, *pql, *pxh, *pxl, *poh, *pol, *pah, *pal, *pwh, *pwl;
    cudaGetSymbolAddress((void**)&px,   g_x);
    cudaGetSymbolAddress((void**)&ptmp, g_tmp);
    cudaGetSymbolAddress((void**)&pqh,  g_qkvh);
    cudaGetSymbolAddress((void**)&pql,  g_qkvl);
    cudaGetSymbolAddress((void**)&pxh,  g_xh);
    cudaGetSymbolAddress((void**)&pxl,  g_xl);
    cudaGetSymbolAddress((void**)&poh,  g_oh);
    cudaGetSymbolAddress((void**)&pol,  g_ol);
    cudaGetSymbolAddress((void**)&pah,  g_ah);
    cudaGetSymbolAddress((void**)&pal,  g_al);
    cudaGetSymbolAddress((void**)&pwh,  g_wh);
    cudaGetSymbolAddress((void**)&pwl,  g_wl);

    int dev = 0, nsm = 148;
    cudaGetDevice(&dev);
    cudaDeviceGetAttribute(&nsm, cudaDevAttrMultiProcessorCount, dev);

    cudaFuncSetAttribute((const void*)attn_tc,
                         cudaFuncAttributeMaxDynamicSharedMemorySize, ATTN_SMEM);
    cudaFuncSetAttribute((const void*)gemm_tc<EPI_BIAS>,
                         cudaFuncAttributeMaxDynamicSharedMemorySize, GEMM_SMEM);
    cudaFuncSetAttribute((const void*)gemm_tc<EPI_RELU>,
                         cudaFuncAttributeMaxDynamicSharedMemorySize, GEMM_SMEM);
    cudaFuncSetAttribute((const void*)gemm_tc<EPI_RES>,
                         cudaFuncAttributeMaxDynamicSharedMemorySize, GEMM_SMEM);
    cudaFuncSetAttribute((const void*)gemm_tc<EPI_QKV>,
                         cudaFuncAttributeMaxDynamicSharedMemorySize, GEMM_SMEM);

#define SPLIT(src, hi, lo, nelem) \
    split_kernel<<<((nelem)/4 + 255)/256, 256>>>((const float4*)(src), (uint2*)(hi), (uint2*)(lo), (nelem)/4)

    init_kernel<<<4096, 256>>>((const float4*)x_in, (float4*)px, (uint2*)pxh, (uint2*)pxl);

    for (int l = 0; l < NLAYERS; l++) {
        const float* Wqkv = ipw + (size_t)l * 3 * DD * DD;
        const float* Bqkv = ipb + (size_t)l * 3 * DD;
        const float* Wout = ow  + (size_t)l * DD * DD;
        const float* Bout = ob  + (size_t)l * DD;
        const float* W1   = f1w + (size_t)l * DFF * DD;
        const float* B1   = f1b + (size_t)l * DFF;
        const float* W2   = f2w + (size_t)l * DD * DFF;
        const float* B2   = f2b + (size_t)l * DD;

        // qkv = x @ Wqkv^T + b  -> split bf16 (Q pre-scaled by 0.125)
        SPLIT(Wqkv, pwh, pwl, 3 * DD * DD);
        gemm_tc<EPI_QKV><<<nsm, 512, GEMM_SMEM>>>(
            pxh, pxl, pwh, pwl, Bqkv, nullptr, nullptr, pqh, pql,
            DD, 3 * DD, 24 * 32, 24);

        // tensor-core block-causal attention -> split o
        attn_tc<<<dim3(SS / 64, BB * HH), 128, ATTN_SMEM>>>(pqh, pql, poh, pol);

        // tmp = x + o @ Wout^T + b
        SPLIT(Wout, pwh, pwl, DD * DD);
        gemm_tc<EPI_RES><<<nsm, 512, GEMM_SMEM>>>(
            poh, pol, pwh, pwl, Bout, px, ptmp, nullptr, nullptr,
            DD, DD, 8 * 32, 8);
        ln_kernel<<<MM, 256>>>(ptmp, n1w + (size_t)l * DD, n1b + (size_t)l * DD,
                               px, pxh, pxl);

        // h = relu(x @ W1^T + b1) -> split h directly
        SPLIT(W1, pwh, pwl, DFF * DD);
        gemm_tc<EPI_RELU><<<nsm, 512, GEMM_SMEM>>>(
            pxh, pxl, pwh, pwl, B1, nullptr, nullptr, pah, pal,
            DD, DFF, 32 * 32, 32);

        // tmp = x + h @ W2^T + b2
        SPLIT(W2, pwh, pwl, DD * DFF);
        gemm_tc<EPI_RES><<<nsm, 512, GEMM_SMEM>>>(
            pah, pal, pwh, pwl, B2, px, ptmp, nullptr, nullptr,
            DFF, DD, 8 * 32, 8);
        ln_kernel<<<MM, 256>>>(ptmp, n2w + (size_t)l * DD, n2b + (size_t)l * DD,
                               (l == NLAYERS - 1) ? out : px, pxh, pxl);
    }
#undef SPLIT
}

// round 16
// speedup vs baseline: 1.1148x; 1.1148x over previous
#include <cuda_runtime.h>
#include <cuda_bf16.h>
#include <math.h>
#include <stdint.h>

// Problem constants
#define BB 4
#define SS 1024
#define DD 1024
#define HH 16
#define DFF 4096
#define NLAYERS 4
#define MM (BB*SS)          // 4096 rows

// ---------------------------------------------------------------------------
// Scratch (static device globals -- no allocation allowed)
// ---------------------------------------------------------------------------
__device__ float g_x  [(size_t)MM * DD];        // activations (fp32, residual)
__device__ float g_tmp[(size_t)MM * DD];        // pre-LN buffer
// split-bf16 activation buffers
__device__ __nv_bfloat16 g_qkvh[(size_t)MM * 3 * DD];     // qkv hi (Q pre-scaled)
__device__ __nv_bfloat16 g_qkvl[(size_t)MM * 3 * DD];     // qkv lo
__device__ __nv_bfloat16 g_xh[(size_t)MM * DD];           // x hi (LN output)
__device__ __nv_bfloat16 g_xl[(size_t)MM * DD];           // x lo
__device__ __nv_bfloat16 g_oh[(size_t)MM * DD];           // attn-out hi
__device__ __nv_bfloat16 g_ol[(size_t)MM * DD];           // attn-out lo
__device__ __nv_bfloat16 g_ah[(size_t)MM * DFF];          // FF hidden hi
__device__ __nv_bfloat16 g_al[(size_t)MM * DFF];          // FF hidden lo
__device__ __nv_bfloat16 g_wh[(size_t)4 * 1024 * 1024];   // W hi
__device__ __nv_bfloat16 g_wl[(size_t)4 * 1024 * 1024];   // W lo

// ---------------------------------------------------------------------------
// Helpers
// ---------------------------------------------------------------------------
__device__ __forceinline__ uint32_t smem_u32(const void* p) {
    uint32_t a;
    asm("{ .reg .u64 t; cvta.to.shared.u64 t, %1; cvt.u32.u64 %0, t; }"
        : "=r"(a) : "l"(p));
    return a;
}
__device__ __forceinline__ uint32_t swz(uint32_t off) {
    return off ^ ((off >> 3) & 0x70);
}
// pack two floats into bf16x2 (hi) and residual bf16x2 (lo)
__device__ __forceinline__ void split2(float x, float y, uint32_t& H, uint32_t& L) {
    __nv_bfloat162 h = __floats2bfloat162_rn(x, y);
    __nv_bfloat162 l = __floats2bfloat162_rn(x - __low2float(h), y - __high2float(h));
    H = *(uint32_t*)&h;
    L = *(uint32_t*)&l;
}

#define CP_ASYNC16(dst, src) \
    asm volatile("cp.async.cg.shared.global [%0], [%1], 16;" :: "r"(dst), "l"(src))
#define CP_COMMIT() asm volatile("cp.async.commit_group;")
#define CP_WAIT1()  asm volatile("cp.async.wait_group 1;")
#define CP_WAIT0()  asm volatile("cp.async.wait_group 0;")

__device__ __forceinline__ void ldsm4(uint32_t* r, uint32_t addr) {
    asm volatile("ldmatrix.sync.aligned.m8n8.x4.shared.b16 {%0,%1,%2,%3}, [%4];"
        : "=r"(r[0]), "=r"(r[1]), "=r"(r[2]), "=r"(r[3]) : "r"(addr));
}
__device__ __forceinline__ void ldsm4t(uint32_t* r, uint32_t addr) {
    asm volatile("ldmatrix.sync.aligned.m8n8.x4.trans.shared.b16 {%0,%1,%2,%3}, [%4];"
        : "=r"(r[0]), "=r"(r[1]), "=r"(r[2]), "=r"(r[3]) : "r"(addr));
}
__device__ __forceinline__ void mma16816(float* d, const uint32_t* a, const uint32_t* b) {
    asm volatile(
        "mma.sync.aligned.m16n8k16.row.col.f32.bf16.bf16.f32 "
        "{%0,%1,%2,%3}, {%4,%5,%6,%7}, {%8,%9}, {%0,%1,%2,%3};"
        : "+f"(d[0]), "+f"(d[1]), "+f"(d[2]), "+f"(d[3])
        : "r"(a[0]), "r"(a[1]), "r"(a[2]), "r"(a[3]), "r"(b[0]), "r"(b[1]));
}

// ---------------------------------------------------------------------------
// fp32 -> (hi, lo) bf16 split (weights only)
// ---------------------------------------------------------------------------
__global__ __launch_bounds__(256)
void split_kernel(const float4* __restrict__ in, uint2* __restrict__ hi,
                  uint2* __restrict__ lo, int n4)
{
    int i = blockIdx.x * 256 + threadIdx.x;
    if (i >= n4) return;
    float4 v = in[i];
    uint2 H, L;
    split2(v.x, v.y, H.x, L.x);
    split2(v.z, v.w, H.y, L.y);
    hi[i] = H;
    lo[i] = L;
}

// ---------------------------------------------------------------------------
// Tensor-core split-bf16 GEMM: C[M,N] = A[M,K] @ B[N,K]^T
// CTA tile 64x128, BK=64, 8 warps (warp tile 32x32; wm 2-way, wn 4-way),
// 2-stage cp.async pipeline, 96KB smem -> TWO CTAs per SM (barrier-decoupled).
// Stage layout: [Ah 8K][Al 8K][Bh 16K][Bl 16K], stride 48K.
// ---------------------------------------------------------------------------
enum { EPI_BIAS = 0, EPI_RELU = 1, EPI_RES = 2, EPI_QKV = 3 };

#define STG_B 49152                    // one stage (48 KB)
#define GEMM_SMEM (2 * STG_B)          // 98304 B -> 2 CTAs/SM

template<int EPI>
__global__ __launch_bounds__(256, 2)
void gemm_tc(const __nv_bfloat16* __restrict__ Ah, const __nv_bfloat16* __restrict__ Al,
             const __nv_bfloat16* __restrict__ Bh, const __nv_bfloat16* __restrict__ Bl,
             const float* __restrict__ bias, const float* __restrict__ Res,
             float* __restrict__ C,
             __nv_bfloat16* __restrict__ Ch, __nv_bfloat16* __restrict__ Cl,
             int K, int N)
{
    extern __shared__ char smg[];
    const uint32_t sbase = smem_u32(smg);
    const int tid  = threadIdx.x;
    const int lane = tid & 31, wid = tid >> 5;       // 8 warps
    const int m0 = blockIdx.y << 6, n0 = blockIdx.x << 7;
    const int wm = (wid & 1) << 5;                   // 0,32
    const int wn = (wid >> 1) << 5;                  // 0,32,64,96

    // loader: 8 threads per 128B row, 32 rows per pass
    const int lrow = tid >> 3;         // 0..31
    const int lkg  = tid & 7;          // 16B group within row
    const __nv_bfloat16* srcA0 = Ah + (size_t)(m0 + lrow) * K + lkg * 8;
    const __nv_bfloat16* srcA1 = Al + (size_t)(m0 + lrow) * K + lkg * 8;
    const __nv_bfloat16* srcB0 = Bh + (size_t)(n0 + lrow) * K + lkg * 8;
    const __nv_bfloat16* srcB1 = Bl + (size_t)(n0 + lrow) * K + lkg * 8;
    const uint32_t ld_sw = swz(lrow * 128 + lkg * 16);
    const size_t rA = (size_t)32 * K;                // 32-row stride in A
    const size_t rB = (size_t)32 * K;                // 32-row stride in B

#define LOAD_STAGE(c, s) do {                                                \
    const size_t kb_ = (size_t)(c) << 6;                                     \
    const uint32_t so_ = (uint32_t)(s) * STG_B;                              \
    /* Ah/Al: 64 rows = 2 passes */                                          \
    CP_ASYNC16(sbase + so_ +     0 + ld_sw,        srcA0 + kb_);             \
    CP_ASYNC16(sbase + so_ +     0 + ld_sw + 4096, srcA0 + kb_ + rA);        \
    CP_ASYNC16(sbase + so_ +  8192 + ld_sw,        srcA1 + kb_);             \
    CP_ASYNC16(sbase + so_ +  8192 + ld_sw + 4096, srcA1 + kb_ + rA);        \
    /* Bh/Bl: 128 rows = 4 passes */                                         \
    _Pragma("unroll")                                                        \
    for (int p_ = 0; p_ < 4; p_++) {                                         \
        CP_ASYNC16(sbase + so_ + 16384 + ld_sw + p_ * 4096,                  \
                   srcB0 + kb_ + (size_t)p_ * rB);                           \
        CP_ASYNC16(sbase + so_ + 32768 + ld_sw + p_ * 4096,                  \
                   srcB1 + kb_ + (size_t)p_ * rB);                           \
    }                                                                        \
} while (0)

    float acc[2][4][4];
#pragma unroll
    for (int mi = 0; mi < 2; mi++)
#pragma unroll
        for (int ni = 0; ni < 4; ni++)
#pragma unroll
            for (int e = 0; e < 4; e++) acc[mi][ni][e] = 0.f;

    const int nc = K >> 6;
    LOAD_STAGE(0, 0); CP_COMMIT();
    LOAD_STAGE(1, 1); CP_COMMIT();
    CP_WAIT1();
    __syncthreads();                       // chunk 0 resident

    const uint32_t arow = wm + (lane & 15);          // 0..47 (A tile 64 rows)
    const uint32_t brow = wn + (lane & 15);          // 0..111 (B tile 128 rows)
    const uint32_t axor = (arow & 7) << 4;
    const uint32_t bxor = (brow & 7) << 4;
    const uint32_t chalf = (lane >> 4) << 4;

    for (int c = 0; c < nc; c++) {
        const uint32_t st = (uint32_t)(c & 1) * STG_B;
        const uint32_t aAh = sbase + st + arow * 128;
        const uint32_t aAl = aAh + 8192;
        const uint32_t aBh = sbase + st + 16384 + brow * 128;
        const uint32_t aBl = aBh + 16384;

#pragma unroll
        for (int kk = 0; kk < 4; kk++) {
            const uint32_t ca = (kk * 32 + chalf) ^ axor;
            const uint32_t cb = (kk * 32 + chalf) ^ bxor;
            uint32_t ah[2][4], al[2][4], bh[4][2], bl[4][2];
#pragma unroll
            for (int mi = 0; mi < 2; mi++) {
                ldsm4(ah[mi], aAh + mi * (16 * 128) + ca);
                ldsm4(al[mi], aAl + mi * (16 * 128) + ca);
            }
#pragma unroll
            for (int nh = 0; nh < 2; nh++) {
                uint32_t r[4];
                ldsm4(r, aBh + nh * (16 * 128) + cb);
                bh[2*nh][0] = r[0]; bh[2*nh][1] = r[2];
                bh[2*nh+1][0] = r[1]; bh[2*nh+1][1] = r[3];
                ldsm4(r, aBl + nh * (16 * 128) + cb);
                bl[2*nh][0] = r[0]; bl[2*nh][1] = r[2];
                bl[2*nh+1][0] = r[1]; bl[2*nh+1][1] = r[3];
            }
#pragma unroll
            for (int mi = 0; mi < 2; mi++)
#pragma unroll
                for (int ni = 0; ni < 4; ni++)
                    mma16816(acc[mi][ni], ah[mi], bh[ni]);
#pragma unroll
            for (int mi = 0; mi < 2; mi++)
#pragma unroll
                for (int ni = 0; ni < 4; ni++)
                    mma16816(acc[mi][ni], ah[mi], bl[ni]);
#pragma unroll
            for (int mi = 0; mi < 2; mi++)
#pragma unroll
                for (int ni = 0; ni < 4; ni++)
                    mma16816(acc[mi][ni], al[mi], bh[ni]);
        }

        // stage (c&1) fully consumed by all warps -> safe to refill
        __syncthreads();
        if (c + 2 < nc) LOAD_STAGE(c + 2, c & 1);
        CP_COMMIT();
        CP_WAIT1();                        // chunk c+1 resident
        __syncthreads();
    }

    // ---- epilogue ----
    const int g = lane >> 2, tig = lane & 3;
    float2 bv[4];
#pragma unroll
    for (int ni = 0; ni < 4; ni++)
        bv[ni] = *(const float2*)(bias + n0 + wn + ni * 8 + tig * 2);

#pragma unroll
    for (int mi = 0; mi < 2; mi++) {
        const int r1 = m0 + wm + mi * 16 + g;
        const int r2 = r1 + 8;
#pragma unroll
        for (int ni = 0; ni < 4; ni++) {
            const int col = n0 + wn + ni * 8 + tig * 2;
            float2 v0 = make_float2(acc[mi][ni][0] + bv[ni].x, acc[mi][ni][1] + bv[ni].y);
            float2 v1 = make_float2(acc[mi][ni][2] + bv[ni].x, acc[mi][ni][3] + bv[ni].y);
            if (EPI == EPI_RELU) {
                v0.x = fmaxf(v0.x, 0.f); v0.y = fmaxf(v0.y, 0.f);
                v1.x = fmaxf(v1.x, 0.f); v1.y = fmaxf(v1.y, 0.f);
                uint32_t H, L;
                split2(v0.x, v0.y, H, L);
                *(uint32_t*)(Ch + (size_t)r1 * N + col) = H;
                *(uint32_t*)(Cl + (size_t)r1 * N + col) = L;
                split2(v1.x, v1.y, H, L);
                *(uint32_t*)(Ch + (size_t)r2 * N + col) = H;
                *(uint32_t*)(Cl + (size_t)r2 * N + col) = L;
            } else if (EPI == EPI_QKV) {
                const float s = (col < 1024) ? 0.125f : 1.0f;
                uint32_t H, L;
                split2(v0.x * s, v0.y * s, H, L);
                *(uint32_t*)(Ch + (size_t)r1 * N + col) = H;
                *(uint32_t*)(Cl + (size_t)r1 * N + col) = L;
                split2(v1.x * s, v1.y * s, H, L);
                *(uint32_t*)(Ch + (size_t)r2 * N + col) = H;
                *(uint32_t*)(Cl + (size_t)r2 * N + col) = L;
            } else {
                if (EPI == EPI_RES) {
                    float2 q0 = *(const float2*)(Res + (size_t)r1 * N + col);
                    float2 q1 = *(const float2*)(Res + (size_t)r2 * N + col);
                    v0.x += q0.x; v0.y += q0.y; v1.x += q1.x; v1.y += q1.y;
                }
                *(float2*)(C + (size_t)r1 * N + col) = v0;
                *(float2*)(C + (size_t)r2 * N + col) = v1;
            }
        }
    }
#undef LOAD_STAGE
}

// ---------------------------------------------------------------------------
// Tensor-core block-causal flash attention (split bf16, mma.m16n8k16).
// CTA = 128 threads (4 warps), one 64-row q-block for one (b,h).  (R14 proven)
// ---------------------------------------------------------------------------
#define ATTN_SMEM 49152

__global__ __launch_bounds__(128, 4)
void attn_tc(const __nv_bfloat16* __restrict__ qvh, const __nv_bfloat16* __restrict__ qvl,
             __nv_bfloat16* __restrict__ oh, __nv_bfloat16* __restrict__ ol)
{
    extern __shared__ char smx[];
    const uint32_t sb  = smem_u32(smx);
    const uint32_t sQh = sb, sQl = sb + 8192;
    const uint32_t sKh = sb + 16384, sKl = sb + 24576;
    const uint32_t sVh = sb + 32768, sVl = sb + 40960;

    const int jq = blockIdx.x;
    const int b  = blockIdx.y >> 4, h = blockIdx.y & 15;
    const int tid = threadIdx.x, lane = tid & 31, w = tid >> 5;
    const int g = lane >> 2, tig = lane & 3;

    const int lrow = tid >> 3;                 // 0..15
    const uint32_t ld_sw = swz(lrow * 128 + (tid & 7) * 16);
    const size_t qtok = (size_t)(b * SS + jq * 64 + lrow) * 3072 + h * 64 + (tid & 7) * 8;
    const size_t ktokb = (size_t)(b * SS + lrow) * 3072 + 1024 + h * 64 + (tid & 7) * 8;

#pragma unroll
    for (int p = 0; p < 4; p++) {
        CP_ASYNC16(sQh + ld_sw + p * 2048, qvh + qtok + (size_t)p * 16 * 3072);
        CP_ASYNC16(sQl + ld_sw + p * 2048, qvl + qtok + (size_t)p * 16 * 3072);
    }
#pragma unroll
    for (int p = 0; p < 4; p++) {
        const size_t t = ktokb + (size_t)p * 16 * 3072;
        CP_ASYNC16(sKh + ld_sw + p * 2048, qvh + t);
        CP_ASYNC16(sKl + ld_sw + p * 2048, qvl + t);
        CP_ASYNC16(sVh + ld_sw + p * 2048, qvh + t + 1024);
        CP_ASYNC16(sVl + ld_sw + p * 2048, qvl + t + 1024);
    }
    CP_COMMIT();

    float accO[8][4];
#pragma unroll
    for (int ni = 0; ni < 8; ni++)
#pragma unroll
        for (int e = 0; e < 4; e++) accO[ni][e] = 0.f;
    float mrow[2] = {-INFINITY, -INFINITY};
    float lsum[2] = {0.f, 0.f};

    const uint32_t arow  = 16 * w + (lane & 15);
    const uint32_t krow  = (lane & 15);
    const uint32_t sxor  = (lane & 7) << 4;
    const uint32_t chalf = (lane >> 4) << 4;
    const uint32_t aQh = sQh + arow * 128, aQl = sQl + arow * 128;

    for (int kb = 0; kb <= jq; kb++) {
        CP_WAIT0();
        __syncthreads();

        float accS[8][4];
#pragma unroll
        for (int ni = 0; ni < 8; ni++)
#pragma unroll
            for (int e = 0; e < 4; e++) accS[ni][e] = 0.f;

#pragma unroll
        for (int ks = 0; ks < 4; ks++) {
            const uint32_t cc = (ks * 32 + chalf) ^ sxor;
            uint32_t qah[4], qal[4];
            ldsm4(qah, aQh + cc);
            ldsm4(qal, aQl + cc);
            uint32_t kbh[8][2], kbl[8][2];
#pragma unroll
            for (int kn = 0; kn < 4; kn++) {
                uint32_t r[4];
                ldsm4(r, sKh + (kn * 16 + krow) * 128 + cc);
                kbh[2*kn][0] = r[0]; kbh[2*kn][1] = r[2];
                kbh[2*kn+1][0] = r[1]; kbh[2*kn+1][1] = r[3];
                ldsm4(r, sKl + (kn * 16 + krow) * 128 + cc);
                kbl[2*kn][0] = r[0]; kbl[2*kn][1] = r[2];
                kbl[2*kn+1][0] = r[1]; kbl[2*kn+1][1] = r[3];
            }
#pragma unroll
            for (int ni = 0; ni < 8; ni++) mma16816(accS[ni], qah, kbh[ni]);
#pragma unroll
            for (int ni = 0; ni < 8; ni++) mma16816(accS[ni], qah, kbl[ni]);
#pragma unroll
            for (int ni = 0; ni < 8; ni++) mma16816(accS[ni], qal, kbh[ni]);
        }
        __syncthreads();

        if (kb < jq) {
            const size_t tn = ktokb + (size_t)(kb + 1) * 64 * 3072;
#pragma unroll
            for (int p = 0; p < 4; p++) {
                CP_ASYNC16(sKh + ld_sw + p * 2048, qvh + tn + (size_t)p * 16 * 3072);
                CP_ASYNC16(sKl + ld_sw + p * 2048, qvl + tn + (size_t)p * 16 * 3072);
            }
            CP_COMMIT();
        }

#pragma unroll
        for (int e = 0; e < 2; e++) {
            float mb = accS[0][2*e];
#pragma unroll
            for (int ni = 0; ni < 8; ni++) {
                mb = fmaxf(mb, accS[ni][2*e]);
                mb = fmaxf(mb, accS[ni][2*e+1]);
            }
            mb = fmaxf(mb, __shfl_xor_sync(0xffffffffu, mb, 1));
            mb = fmaxf(mb, __shfl_xor_sync(0xffffffffu, mb, 2));
            const float mnew = fmaxf(mrow[e], mb);
            const float alpha = __expf(mrow[e] - mnew);
            float rs = 0.f;
#pragma unroll
            for (int ni = 0; ni < 8; ni++) {
                float p0 = __expf(accS[ni][2*e]   - mnew);
                float p1 = __expf(accS[ni][2*e+1] - mnew);
                accS[ni][2*e] = p0; accS[ni][2*e+1] = p1;
                rs += p0 + p1;
            }
            rs += __shfl_xor_sync(0xffffffffu, rs, 1);
            rs += __shfl_xor_sync(0xffffffffu, rs, 2);
            lsum[e] = lsum[e] * alpha + rs;
            mrow[e] = mnew;
#pragma unroll
            for (int ni = 0; ni < 8; ni++) {
                accO[ni][2*e]   *= alpha;
                accO[ni][2*e+1] *= alpha;
            }
        }

#pragma unroll
        for (int j = 0; j < 4; j++) {
            uint32_t ph[4], pl[4];
            split2(accS[2*j][0],   accS[2*j][1],   ph[0], pl[0]);
            split2(accS[2*j][2],   accS[2*j][3],   ph[1], pl[1]);
            split2(accS[2*j+1][0], accS[2*j+1][1], ph[2], pl[2]);
            split2(accS[2*j+1][2], accS[2*j+1][3], ph[3], pl[3]);
            const uint32_t vbase = (j * 16 + krow) * 128;
            uint32_t bvh[8][2], bvl[8][2];
#pragma unroll
            for (int ng = 0; ng < 4; ng++) {
                const uint32_t cc = (ng * 32 + chalf) ^ sxor;
                uint32_t r[4];
                ldsm4t(r, sVh + vbase + cc);
                bvh[2*ng][0] = r[0]; bvh[2*ng][1] = r[1];
                bvh[2*ng+1][0] = r[2]; bvh[2*ng+1][1] = r[3];
                ldsm4t(r, sVl + vbase + cc);
                bvl[2*ng][0] = r[0]; bvl[2*ng][1] = r[1];
                bvl[2*ng+1][0] = r[2]; bvl[2*ng+1][1] = r[3];
            }
#pragma unroll
            for (int ni = 0; ni < 8; ni++) mma16816(accO[ni], ph, bvh[ni]);
#pragma unroll
            for (int ni = 0; ni < 8; ni++) mma16816(accO[ni], ph, bvl[ni]);
#pragma unroll
            for (int ni = 0; ni < 8; ni++) mma16816(accO[ni], pl, bvh[ni]);
        }
        __syncthreads();

        if (kb < jq) {
            const size_t tn = ktokb + (size_t)(kb + 1) * 64 * 3072 + 1024;
#pragma unroll
            for (int p = 0; p < 4; p++) {
                CP_ASYNC16(sVh + ld_sw + p * 2048, qvh + tn + (size_t)p * 16 * 3072);
                CP_ASYNC16(sVl + ld_sw + p * 2048, qvl + tn + (size_t)p * 16 * 3072);
            }
            CP_COMMIT();
        }
    }

    const size_t orow0 = (size_t)(b * SS + jq * 64 + 16 * w + g);
#pragma unroll
    for (int e = 0; e < 2; e++) {
        const float inv = 1.0f / lsum[e];
        const size_t rbase = (orow0 + 8 * e) * (size_t)DD + h * 64 + tig * 2;
#pragma unroll
        for (int ni = 0; ni < 8; ni++) {
            uint32_t H, L;
            split2(accO[ni][2*e] * inv, accO[ni][2*e+1] * inv, H, L);
            *(uint32_t*)(oh + rbase + ni * 8) = H;
            *(uint32_t*)(ol + rbase + ni * 8) = L;
        }
    }
}

// ---------------------------------------------------------------------------
// LayerNorm over D=1024, one block (256 threads) per row.
// ---------------------------------------------------------------------------
__global__ __launch_bounds__(256)
void ln_kernel(const float* __restrict__ in, const float* __restrict__ w,
               const float* __restrict__ b, float* __restrict__ out,
               __nv_bfloat16* __restrict__ oh, __nv_bfloat16* __restrict__ ol)
{
    __shared__ float s_sum[8], s_sq[8], s_bc[2];
    const int row = blockIdx.x, tid = threadIdx.x;
    float4 v = ((const float4*)(in + (size_t)row * 1024))[tid];
    float s = v.x + v.y + v.z + v.w;
    float q = v.x * v.x + v.y * v.y + v.z * v.z + v.w * v.w;
#pragma unroll
    for (int o = 16; o; o >>= 1) {
        s += __shfl_xor_sync(0xffffffffu, s, o);
        q += __shfl_xor_sync(0xffffffffu, q, o);
    }
    if ((tid & 31) == 0) { s_sum[tid >> 5] = s; s_sq[tid >> 5] = q; }
    __syncthreads();
    if (tid == 0) {
        float ts = 0.f, tq = 0.f;
#pragma unroll
        for (int i = 0; i < 8; i++) { ts += s_sum[i]; tq += s_sq[i]; }
        float mu  = ts * (1.f / 1024.f);
        float var = tq * (1.f / 1024.f) - mu * mu;
        s_bc[0] = mu;
        s_bc[1] = rsqrtf(var + 1e-5f);
    }
    __syncthreads();
    float mu = s_bc[0], rs = s_bc[1];
    float4 wv = ((const float4*)w)[tid];
    float4 bv = ((const float4*)b)[tid];
    float4 ov;
    ov.x = (v.x - mu) * rs * wv.x + bv.x;
    ov.y = (v.y - mu) * rs * wv.y + bv.y;
    ov.z = (v.z - mu) * rs * wv.z + bv.z;
    ov.w = (v.w - mu) * rs * wv.w + bv.w;
    ((float4*)(out + (size_t)row * 1024))[tid] = ov;
    uint2 H, L;
    split2(ov.x, ov.y, H.x, L.x);
    split2(ov.z, ov.w, H.y, L.y);
    ((uint2*)(oh + (size_t)row * 1024))[tid] = H;
    ((uint2*)(ol + (size_t)row * 1024))[tid] = L;
}

// initial copy: x -> working fp32 buffer + split bf16
__global__ __launch_bounds__(256)
void init_kernel(const float4* __restrict__ s, float4* __restrict__ d,
                 uint2* __restrict__ hi, uint2* __restrict__ lo)
{
    int i = blockIdx.x * 256 + threadIdx.x;
    float4 v = s[i];
    d[i] = v;
    uint2 H, L;
    split2(v.x, v.y, H.x, L.x);
    split2(v.z, v.w, H.y, L.y);
    hi[i] = H;
    lo[i] = L;
}

// ---------------------------------------------------------------------------
// Host orchestration (graph-capturable: kernel launches only)
// ---------------------------------------------------------------------------
extern "C" void kernel_launch(void* const* d_in, const int* in_sizes, int n_in,
                              void* d_out, int out_size)
{
    (void)in_sizes; (void)n_in; (void)out_size;
    const float* x_in = (const float*)d_in[0];
    const float* ipw  = (const float*)d_in[1];   // [L,3072,1024]
    const float* ipb  = (const float*)d_in[2];   // [L,3072]
    const float* ow   = (const float*)d_in[3];   // [L,1024,1024]
    const float* ob   = (const float*)d_in[4];   // [L,1024]
    const float* n1w  = (const float*)d_in[5];
    const float* n1b  = (const float*)d_in[6];
    const float* f1w  = (const float*)d_in[7];   // [L,4096,1024]
    const float* f1b  = (const float*)d_in[8];   // [L,4096]
    const float* f2w  = (const float*)d_in[9];   // [L,1024,4096]
    const float* f2b  = (const float*)d_in[10];  // [L,1024]
    const float* n2w  = (const float*)d_in[11];
    const float* n2b  = (const float*)d_in[12];
    float* out = (float*)d_out;

    float *px, *ptmp;
    __nv_bfloat16 *pqh, *pql, *pxh, *pxl, *poh, *pol, *pah, *pal, *pwh, *pwl;
    cudaGetSymbolAddress((void**)&px,   g_x);
    cudaGetSymbolAddress((void**)&ptmp, g_tmp);
    cudaGetSymbolAddress((void**)&pqh,  g_qkvh);
    cudaGetSymbolAddress((void**)&pql,  g_qkvl);
    cudaGetSymbolAddress((void**)&pxh,  g_xh);
    cudaGetSymbolAddress((void**)&pxl,  g_xl);
    cudaGetSymbolAddress((void**)&poh,  g_oh);
    cudaGetSymbolAddress((void**)&pol,  g_ol);
    cudaGetSymbolAddress((void**)&pah,  g_ah);
    cudaGetSymbolAddress((void**)&pal,  g_al);
    cudaGetSymbolAddress((void**)&pwh,  g_wh);
    cudaGetSymbolAddress((void**)&pwl,  g_wl);

    cudaFuncSetAttribute((const void*)attn_tc,
                         cudaFuncAttributeMaxDynamicSharedMemorySize, ATTN_SMEM);
    cudaFuncSetAttribute((const void*)gemm_tc<EPI_BIAS>,
                         cudaFuncAttributeMaxDynamicSharedMemorySize, GEMM_SMEM);
    cudaFuncSetAttribute((const void*)gemm_tc<EPI_RELU>,
                         cudaFuncAttributeMaxDynamicSharedMemorySize, GEMM_SMEM);
    cudaFuncSetAttribute((const void*)gemm_tc<EPI_RES>,
                         cudaFuncAttributeMaxDynamicSharedMemorySize, GEMM_SMEM);
    cudaFuncSetAttribute((const void*)gemm_tc<EPI_QKV>,
                         cudaFuncAttributeMaxDynamicSharedMemorySize, GEMM_SMEM);

#define SPLIT(src, hi, lo, nelem) \
    split_kernel<<<((nelem)/4 + 255)/256, 256>>>((const float4*)(src), (uint2*)(hi), (uint2*)(lo), (nelem)/4)

    init_kernel<<<4096, 256>>>((const float4*)x_in, (float4*)px, (uint2*)pxh, (uint2*)pxl);

    for (int l = 0; l < NLAYERS; l++) {
        const float* Wqkv = ipw + (size_t)l * 3 * DD * DD;
        const float* Bqkv = ipb + (size_t)l * 3 * DD;
        const float* Wout = ow  + (size_t)l * DD * DD;
        const float* Bout = ob  + (size_t)l * DD;
        const float* W1   = f1w + (size_t)l * DFF * DD;
        const float* B1   = f1b + (size_t)l * DFF;
        const float* W2   = f2w + (size_t)l * DD * DFF;
        const float* B2   = f2b + (size_t)l * DD;

        // qkv = x @ Wqkv^T + b  -> split bf16 (Q pre-scaled by 0.125)
        SPLIT(Wqkv, pwh, pwl, 3 * DD * DD);
        gemm_tc<EPI_QKV><<<dim3(24, 64), 256, GEMM_SMEM>>>(
            pxh, pxl, pwh, pwl, Bqkv, nullptr, nullptr, pqh, pql, DD, 3 * DD);

        // tensor-core block-causal attention -> split o
        attn_tc<<<dim3(SS / 64, BB * HH), 128, ATTN_SMEM>>>(pqh, pql, poh, pol);

        // tmp = x + o @ Wout^T + b
        SPLIT(Wout, pwh, pwl, DD * DD);
        gemm_tc<EPI_RES><<<dim3(8, 64), 256, GEMM_SMEM>>>(
            poh, pol, pwh, pwl, Bout, px, ptmp, nullptr, nullptr, DD, DD);
        ln_kernel<<<MM, 256>>>(ptmp, n1w + (size_t)l * DD, n1b + (size_t)l * DD,
                               px, pxh, pxl);

        // h = relu(x @ W1^T + b1) -> split h directly
        SPLIT(W1, pwh, pwl, DFF * DD);
        gemm_tc<EPI_RELU><<<dim3(32, 64), 256, GEMM_SMEM>>>(
            pxh, pxl, pwh, pwl, B1, nullptr, nullptr, pah, pal, DD, DFF);

        // tmp = x + h @ W2^T + b2
        SPLIT(W2, pwh, pwl, DD * DFF);
        gemm_tc<EPI_RES><<<dim3(8, 64), 256, GEMM_SMEM>>>(
            pah, pal, pwh, pwl, B2, px, ptmp, nullptr, nullptr, DFF, DD);
        // x = LN2(tmp) (last layer writes final output)
        ln_kernel<<<MM, 256>>>(ptmp, n2w + (size_t)l * DD, n2b + (size_t)l * DD,
                               (l == NLAYERS - 1) ? out : px, pxh, pxl);
    }
#undef SPLIT
}